// round 1
// baseline (speedup 1.0000x reference)
#include <cuda_runtime.h>
#include <math.h>

#define D 128
#define G 256
#define BMAX 8192
#define NODES_PER_WARP 16

__device__ float g_w[D];      // Wp @ We[:G]
__device__ float g_c;         // bp . We[:G]
__device__ float g_accum[BMAX];

// ---------------------------------------------------------------------------
// Kernel 1: zero accumulators, fold Wp/bp into We's graph-embed half.
// Launch: 32 blocks x 256 threads (8192 threads = 256 warps).
//   thread t zeroes g_accum[t]; warps 0..127 compute g_w[warp]; warp 128 -> g_c
// ---------------------------------------------------------------------------
__global__ void dgmg_precompute(const float* __restrict__ Wp,
                                const float* __restrict__ bp,
                                const float* __restrict__ We,
                                int B) {
    int gt = blockIdx.x * blockDim.x + threadIdx.x;
    if (gt < BMAX) g_accum[gt] = 0.0f;

    int gw   = gt >> 5;
    int lane = gt & 31;
    if (gw < D) {
        const float* row = Wp + (size_t)gw * G;
        float s = 0.0f;
        #pragma unroll
        for (int i = 0; i < G / 32; i++) {
            int idx = lane + 32 * i;
            s += row[idx] * We[idx];
        }
        #pragma unroll
        for (int off = 16; off > 0; off >>= 1)
            s += __shfl_xor_sync(0xffffffffu, s, off);
        if (lane == 0) g_w[gw] = s;
    } else if (gw == D) {
        float s = 0.0f;
        #pragma unroll
        for (int i = 0; i < G / 32; i++) {
            int idx = lane + 32 * i;
            s += bp[idx] * We[idx];
        }
        #pragma unroll
        for (int off = 16; off > 0; off >>= 1)
            s += __shfl_xor_sync(0xffffffffu, s, off);
        if (lane == 0) g_c = s;
    }
}

// ---------------------------------------------------------------------------
// Kernel 2: stream hv once. One warp handles NODES_PER_WARP consecutive nodes.
// Per node: coalesced float4 row load, two warp-reduced dots, sigmoid gate,
// run-length aggregation over sorted seg_ids, rare atomicAdd at boundaries.
// ---------------------------------------------------------------------------
__global__ void __launch_bounds__(256)
dgmg_node_pass(const float* __restrict__ hv,
               const float* __restrict__ Wg,
               const float* __restrict__ bg,
               const int*   __restrict__ seg,
               int N) {
    const int lane = threadIdx.x & 31;
    const int warpsPerBlock = blockDim.x >> 5;
    const int wid = blockIdx.x * warpsPerBlock + (threadIdx.x >> 5);

    int start = wid * NODES_PER_WARP;
    if (start >= N) return;
    int end = min(start + NODES_PER_WARP, N);

    const float  bg0 = bg[0];
    const float  c0  = g_c;
    const float4 wg4 = reinterpret_cast<const float4*>(Wg)[lane];
    const float4 w4  = reinterpret_cast<const float4*>(g_w)[lane];

    int   cur_seg = seg[start];
    float acc     = 0.0f;

    #pragma unroll 2
    for (int n = start; n < end; n++) {
        const float4 h = reinterpret_cast<const float4*>(hv + (size_t)n * D)[lane];
        int s_id = seg[n];

        float d1 = h.x * wg4.x + h.y * wg4.y + h.z * wg4.z + h.w * wg4.w;
        float d2 = h.x * w4.x  + h.y * w4.y  + h.z * w4.z  + h.w * w4.w;
        #pragma unroll
        for (int off = 16; off > 0; off >>= 1) {
            d1 += __shfl_xor_sync(0xffffffffu, d1, off);
            d2 += __shfl_xor_sync(0xffffffffu, d2, off);
        }

        float gate    = 1.0f / (1.0f + expf(-(d1 + bg0)));
        float contrib = gate * (d2 + c0);

        if (s_id != cur_seg) {
            if (lane == 0) atomicAdd(&g_accum[cur_seg], acc);
            acc     = 0.0f;
            cur_seg = s_id;
        }
        acc += contrib;
    }
    if (lane == 0) atomicAdd(&g_accum[cur_seg], acc);
}

// ---------------------------------------------------------------------------
// Kernel 3: one warp per graph. Gather src embedding, dot with We[G:],
// combine with accumulated graph term, stable log-sigmoid, pick by action a.
// ---------------------------------------------------------------------------
__global__ void __launch_bounds__(256)
dgmg_finalize(const float* __restrict__ hv,
              const float* __restrict__ We,
              const float* __restrict__ be,
              const int*   __restrict__ last_idx,
              const int*   __restrict__ a,
              float*       __restrict__ out,
              int B) {
    const int lane = threadIdx.x & 31;
    const int warpsPerBlock = blockDim.x >> 5;
    const int b = blockIdx.x * warpsPerBlock + (threadIdx.x >> 5);
    if (b >= B) return;

    const int li = last_idx[b];
    const float4 h  = reinterpret_cast<const float4*>(hv + (size_t)li * D)[lane];
    const float4 we = reinterpret_cast<const float4*>(We + G)[lane];

    float d = h.x * we.x + h.y * we.y + h.z * we.z + h.w * we.w;
    #pragma unroll
    for (int off = 16; off > 0; off >>= 1)
        d += __shfl_xor_sync(0xffffffffu, d, off);

    if (lane == 0) {
        float logit = g_accum[b] + d + be[0];
        float x = (a[b] != 0) ? logit : -logit;
        // stable log-sigmoid
        float ls = (x >= 0.0f) ? -log1pf(expf(-x)) : (x - log1pf(expf(x)));
        out[b] = ls;
    }
}

// ---------------------------------------------------------------------------
extern "C" void kernel_launch(void* const* d_in, const int* in_sizes, int n_in,
                              void* d_out, int out_size) {
    const float* hv       = (const float*)d_in[0];
    const float* Wg       = (const float*)d_in[1];
    const float* bg       = (const float*)d_in[2];
    const float* Wp       = (const float*)d_in[3];
    const float* bp       = (const float*)d_in[4];
    const float* We       = (const float*)d_in[5];
    const float* be       = (const float*)d_in[6];
    const int*   seg_ids  = (const int*)d_in[7];
    const int*   last_idx = (const int*)d_in[8];
    const int*   a        = (const int*)d_in[9];
    float* out = (float*)d_out;

    const int N = in_sizes[0] / D;
    const int B = in_sizes[8];

    // K1: zero accum + fold weights (needs 8192 threads)
    dgmg_precompute<<<BMAX / 256, 256>>>(Wp, bp, We, B);

    // K2: node streaming pass
    int warps  = (N + NODES_PER_WARP - 1) / NODES_PER_WARP;
    int blocks = (warps + 7) / 8;
    dgmg_node_pass<<<blocks, 256>>>(hv, Wg, bg, seg_ids, N);

    // K3: per-graph finalize (8 warps/block)
    int fblocks = (B + 7) / 8;
    dgmg_finalize<<<fblocks, 256>>>(hv, We, be, last_idx, a, out, B);
}